// round 8
// baseline (speedup 1.0000x reference)
#include <cuda_runtime.h>
#include <cuda_fp16.h>
#include <cstdint>

// EdgeNetwork via mma.sync m16n8k16 fp16 error-compensated split.
// H = E@W + b ; messages[g,i] = sum_j relu(H[g, 32i+j]) * s[g,j]
// E = Eh + El, W = Wh + Wl (fp16 each). H ~= EhWh + EhWl + ElWh.
// R8: 1 output column per warp (4 ct-groups), bias via mma C operand,
// ~75 regs -> 3 CTAs/SM.

#define NTHREADS 256

// smem byte offsets
#define SM_EH   0                      // [128 rows][4 q] uint2 = 4KB
#define SM_EL   4096                   // 4KB
#define SM_SP   8192                   // [4][128][4] float2 = 16KB
#define SM_TOTAL 24576

// Pre-split W, fragment-permuted: entry [n][q] = { h2(w[2q][n],w[2q+1][n]), h2(w[2q+8][n],w[2q+9][n]) }
__device__ uint2 d_Wh[4096];
__device__ uint2 d_Wl[4096];

__device__ __forceinline__ void split16(float v, __half& hi, __half& lo) {
    hi = __float2half_rn(v);
    lo = __float2half_rn(v - __half2float(hi));
}
__device__ __forceinline__ uint32_t pack_h2(__half a, __half b) {
    __half2 h = __halves2half2(a, b);
    return *reinterpret_cast<uint32_t*>(&h);
}

__global__ void prep_w(const float* __restrict__ W) {
    int idx = blockIdx.x * 256 + threadIdx.x;   // 0..4095 over [n][q]
    int n = idx >> 2, q = idx & 3;
    __half h0, l0, h1, l1, h2v, l2, h3, l3;
    split16(W[(2 * q)     * 1024 + n], h0, l0);
    split16(W[(2 * q + 1) * 1024 + n], h1, l1);
    split16(W[(2 * q + 8) * 1024 + n], h2v, l2);
    split16(W[(2 * q + 9) * 1024 + n], h3, l3);
    d_Wh[idx] = make_uint2(pack_h2(h0, h1), pack_h2(h2v, h3));
    d_Wl[idx] = make_uint2(pack_h2(l0, l1), pack_h2(l2, l3));
}

// D = A*B + D
__device__ __forceinline__ void mma16(float* d, uint2 arow, uint2 arow8, uint2 b) {
    asm volatile(
        "mma.sync.aligned.m16n8k16.row.col.f32.f16.f16.f32 "
        "{%0,%1,%2,%3}, {%4,%5,%6,%7}, {%8,%9}, {%0,%1,%2,%3};"
        : "+f"(d[0]), "+f"(d[1]), "+f"(d[2]), "+f"(d[3])
        : "r"(arow.x), "r"(arow8.x), "r"(arow.y), "r"(arow8.y),
          "r"(b.x), "r"(b.y));
}
// D = A*B + {cx,cy,cx,cy}  (bias seeding, no MOVs)
__device__ __forceinline__ void mma16c(float* d, uint2 arow, uint2 arow8, uint2 b,
                                       float cx, float cy) {
    asm volatile(
        "mma.sync.aligned.m16n8k16.row.col.f32.f16.f16.f32 "
        "{%0,%1,%2,%3}, {%4,%5,%6,%7}, {%8,%9}, {%10,%11,%10,%11};"
        : "=f"(d[0]), "=f"(d[1]), "=f"(d[2]), "=f"(d[3])
        : "r"(arow.x), "r"(arow8.x), "r"(arow.y), "r"(arow8.y),
          "r"(b.x), "r"(b.y), "f"(cx), "f"(cy));
}

__global__ __launch_bounds__(NTHREADS, 3) void edge_net_mma(
    const float* __restrict__ states,
    const float* __restrict__ edges,
    const float* __restrict__ bg,
    float* __restrict__ out)
{
    extern __shared__ char sm[];
    const uint2* EH = (const uint2*)(sm + SM_EH);
    const uint2* EL = (const uint2*)(sm + SM_EL);
    const float2* SP = (const float2*)(sm + SM_SP);

    const int tid = threadIdx.x;
    const int eb = blockIdx.x & 511;       // edge block (128 edges)
    const int cb = blockIdx.x >> 9;        // column quarter (256 cols)
    const int gbase = eb * 128;
    const int col0 = cb * 256;

    const int w = tid >> 5, lane = tid & 31;
    const int g = lane >> 2;               // groupID: row-in-tile / B-col
    const int q = lane & 3;                // threadID-in-group

    // ---- W + bias fragments -> registers (coalesced, L2-resident) ----
    uint2 wh[4], wl[4];
    float2 b2[4];
    #pragma unroll
    for (int ct = 0; ct < 4; ct++) {
        int n = col0 + w * 32 + ct * 8 + g;
        wh[ct] = d_Wh[n * 4 + q];
        wl[ct] = d_Wl[n * 4 + q];
        b2[ct] = *(const float2*)(bg + col0 + w * 32 + ct * 8 + 2 * q);
    }

    // ---- Stage + split edges: EH/EL[row][q] ----
    {
        const float2* er = (const float2*)(edges + (size_t)gbase * 16);
        #pragma unroll
        for (int k = 0; k < 2; k++) {
            int item = tid + k * 256;          // 0..511 over [row][q]
            int row = item >> 2, qq = item & 3;
            float2 v0 = er[row * 8 + qq];
            float2 v1 = er[row * 8 + qq + 4];
            __half h0, l0, h1, l1, h2v, l2, h3, l3;
            split16(v0.x, h0, l0);  split16(v0.y, h1, l1);
            split16(v1.x, h2v, l2); split16(v1.y, h3, l3);
            ((uint2*)(sm + SM_EH))[item] = make_uint2(pack_h2(h0, h1), pack_h2(h2v, h3));
            ((uint2*)(sm + SM_EL))[item] = make_uint2(pack_h2(l0, l1), pack_h2(l2, l3));
        }
    }
    // ---- Stage states: SP[a][row][q2] = {s[row][8a+2q2], s[row][8a+2q2+1]} ----
    {
        const float4* sv = (const float4*)(states + (size_t)gbase * 32);
        #pragma unroll
        for (int k = 0; k < 4; k++) {
            int idx = tid + k * 256;           // 0..1023 over [row][f4]
            int row = idx >> 3, f4 = idx & 7;
            float4 v = sv[idx];
            int a = f4 >> 1, q2 = (f4 & 1) * 2;
            *(float4*)((float*)(sm + SM_SP) + ((a * 128 + row) * 4 + q2) * 2) = v;
        }
    }
    __syncthreads();

    const int i = cb * 8 + w;              // this warp's output column

    #pragma unroll
    for (int pass = 0; pass < 4; pass++) {
        const int rb = pass * 32;

        uint2 ah[2][2], al[2][2];          // [rt][row / row+8]
        #pragma unroll
        for (int rt = 0; rt < 2; rt++) {
            int row = rb + rt * 16 + g;
            ah[rt][0] = EH[row * 4 + q];
            ah[rt][1] = EH[(row + 8) * 4 + q];
            al[rt][0] = EL[row * 4 + q];
            al[rt][1] = EL[(row + 8) * 4 + q];
        }

        float mm[2][2] = {{0.f, 0.f}, {0.f, 0.f}};   // [rt][row-half]

        #pragma unroll
        for (int ct = 0; ct < 4; ct++) {   // ct == state group a
            float2 s0[2], s1[2];
            #pragma unroll
            for (int rt = 0; rt < 2; rt++) {
                int row = rb + rt * 16 + g;
                s0[rt] = SP[ct * 512 + row * 4 + q];
                s1[rt] = SP[ct * 512 + (row + 8) * 4 + q];
            }

            float d[2][4];
            mma16c(d[0], ah[0][0], ah[0][1], wh[ct], b2[ct].x, b2[ct].y);
            mma16c(d[1], ah[1][0], ah[1][1], wh[ct], b2[ct].x, b2[ct].y);
            mma16(d[0], ah[0][0], ah[0][1], wl[ct]);
            mma16(d[1], ah[1][0], ah[1][1], wl[ct]);
            mma16(d[0], al[0][0], al[0][1], wh[ct]);
            mma16(d[1], al[1][0], al[1][1], wh[ct]);

            #pragma unroll
            for (int rt = 0; rt < 2; rt++) {
                mm[rt][0] = fmaf(fmaxf(d[rt][0], 0.f), s0[rt].x, mm[rt][0]);
                mm[rt][0] = fmaf(fmaxf(d[rt][1], 0.f), s0[rt].y, mm[rt][0]);
                mm[rt][1] = fmaf(fmaxf(d[rt][2], 0.f), s1[rt].x, mm[rt][1]);
                mm[rt][1] = fmaf(fmaxf(d[rt][3], 0.f), s1[rt].y, mm[rt][1]);
            }
        }

        // ---- Reduce over q (quad) and store ----
        #pragma unroll
        for (int rt = 0; rt < 2; rt++) {
            float v0 = mm[rt][0], v1 = mm[rt][1];
            v0 += __shfl_xor_sync(0xffffffffu, v0, 1);
            v0 += __shfl_xor_sync(0xffffffffu, v0, 2);
            v1 += __shfl_xor_sync(0xffffffffu, v1, 1);
            v1 += __shfl_xor_sync(0xffffffffu, v1, 2);
            if (q == 0) {
                int row = rb + rt * 16 + g;
                out[(size_t)(gbase + row) * 32 + i] = v0;
                out[(size_t)(gbase + row + 8) * 32 + i] = v1;
            }
        }
    }
}

extern "C" void kernel_launch(void* const* d_in, const int* in_sizes, int n_in,
                              void* d_out, int out_size)
{
    const float* states = (const float*)d_in[0];  // [16, 4096, 32]
    const float* edges  = (const float*)d_in[1];  // [16, 4096, 16]
    const float* W      = (const float*)d_in[2];  // [16, 1024]
    const float* b      = (const float*)d_in[3];  // [1024]
    float* out          = (float*)d_out;          // [16, 4096, 32]

    (void)in_sizes; (void)n_in; (void)out_size;

    static int configured = 0;
    if (!configured) {
        cudaFuncSetAttribute(edge_net_mma,
                             cudaFuncAttributeMaxDynamicSharedMemorySize, SM_TOTAL);
        configured = 1;
    }
    prep_w<<<16, 256>>>(W);
    edge_net_mma<<<2048, NTHREADS, SM_TOTAL>>>(states, edges, b, out);
}

// round 9
// speedup vs baseline: 1.1864x; 1.1864x over previous
#include <cuda_runtime.h>
#include <cuda_fp16.h>
#include <cstdint>

// EdgeNetwork via mma.sync m16n8k16 fp16 error-compensated split.
// H = E@W + b ; messages[g,i] = sum_j relu(H[g, 32i+j]) * s[g,j]
// E = Eh + El, W = Wh + Wl (fp16 each). H ~= EhWh + EhWl + ElWh.
// R9: grid 1024 (2 cols/warp), hi/lo interleaved uint4 fragments, bias via mma
// C-operand, packed f32x2 epilogue, 16-row steps for register discipline.

#define NTHREADS 256
typedef unsigned long long u64;

// Pre-split W, fragment-permuted, hi/lo interleaved:
// d_Whl[n*4+q] = { h2(wh[2q][n],wh[2q+1][n]), h2(wh[2q+8][n],wh[2q+9][n]),
//                  h2(wl[2q][n],wl[2q+1][n]), h2(wl[2q+8][n],wl[2q+9][n]) }
__device__ uint4 d_Whl[4096];

__device__ __forceinline__ void split16(float v, __half& hi, __half& lo) {
    hi = __float2half_rn(v);
    lo = __float2half_rn(v - __half2float(hi));
}
__device__ __forceinline__ uint32_t pack_h2(__half a, __half b) {
    __half2 h = __halves2half2(a, b);
    return *reinterpret_cast<uint32_t*>(&h);
}
__device__ __forceinline__ u64 pack_f2(float lo, float hi) {
    u64 r; asm("mov.b64 %0, {%1, %2};" : "=l"(r) : "f"(lo), "f"(hi)); return r;
}
__device__ __forceinline__ void unpack_f2(u64 v, float& lo, float& hi) {
    asm("mov.b64 {%0, %1}, %2;" : "=f"(lo), "=f"(hi) : "l"(v));
}
__device__ __forceinline__ void fma2(u64& acc, u64 a, u64 b) {
    asm("fma.rn.f32x2 %0, %1, %2, %0;" : "+l"(acc) : "l"(a), "l"(b));
}

__global__ void prep_w(const float* __restrict__ W) {
    int idx = blockIdx.x * 256 + threadIdx.x;   // 0..4095 over [n][q]
    int n = idx >> 2, q = idx & 3;
    __half h0, l0, h1, l1, h2v, l2, h3, l3;
    split16(W[(2 * q)     * 1024 + n], h0, l0);
    split16(W[(2 * q + 1) * 1024 + n], h1, l1);
    split16(W[(2 * q + 8) * 1024 + n], h2v, l2);
    split16(W[(2 * q + 9) * 1024 + n], h3, l3);
    d_Whl[idx] = make_uint4(pack_h2(h0, h1), pack_h2(h2v, h3),
                            pack_h2(l0, l1), pack_h2(l2, l3));
}

// D = A*B + D
__device__ __forceinline__ void mma16(float* d, uint32_t a0, uint32_t a1,
                                      uint32_t a2, uint32_t a3,
                                      uint32_t b0, uint32_t b1) {
    asm volatile(
        "mma.sync.aligned.m16n8k16.row.col.f32.f16.f16.f32 "
        "{%0,%1,%2,%3}, {%4,%5,%6,%7}, {%8,%9}, {%0,%1,%2,%3};"
        : "+f"(d[0]), "+f"(d[1]), "+f"(d[2]), "+f"(d[3])
        : "r"(a0), "r"(a1), "r"(a2), "r"(a3), "r"(b0), "r"(b1));
}
// D = A*B + {cx,cy,cx,cy}
__device__ __forceinline__ void mma16c(float* d, uint32_t a0, uint32_t a1,
                                       uint32_t a2, uint32_t a3,
                                       uint32_t b0, uint32_t b1,
                                       float cx, float cy) {
    asm volatile(
        "mma.sync.aligned.m16n8k16.row.col.f32.f16.f16.f32 "
        "{%0,%1,%2,%3}, {%4,%5,%6,%7}, {%8,%9}, {%10,%11,%10,%11};"
        : "=f"(d[0]), "=f"(d[1]), "=f"(d[2]), "=f"(d[3])
        : "r"(a0), "r"(a1), "r"(a2), "r"(a3), "r"(b0), "r"(b1),
          "f"(cx), "f"(cy));
}

__global__ __launch_bounds__(NTHREADS, 2) void edge_net_mma(
    const float* __restrict__ states,
    const float* __restrict__ edges,
    const float* __restrict__ bg,
    float* __restrict__ out)
{
    // EHL[row][q] = {Eh pair lo-k, Eh pair hi-k, El pair lo-k, El pair hi-k}
    __shared__ uint4  EHL[128 * 4];            // 8 KB
    __shared__ float2 SP[4 * 128 * 4];         // 16 KB : [a][row][q2]

    const int tid = threadIdx.x;
    const int eb = blockIdx.x & 511;           // edge block (128 edges)
    const int cb = blockIdx.x >> 9;            // column half (512 cols)
    const int gbase = eb * 128;
    const int col0 = cb * 512;

    const int w = tid >> 5, lane = tid & 31;
    const int g = lane >> 2;                   // groupID: row-in-tile / B-col
    const int q = lane & 3;                    // threadID-in-group

    // ---- W + bias fragments -> registers (coalesced, L2-resident) ----
    uint4 whl[8];
    float2 b2[8];
    #pragma unroll
    for (int ct = 0; ct < 8; ct++) {
        int n = col0 + w * 64 + ct * 8 + g;
        whl[ct] = d_Whl[n * 4 + q];
        b2[ct] = *(const float2*)(bg + col0 + w * 64 + ct * 8 + 2 * q);
    }

    // ---- Stage + split edges ----
    {
        const float2* er = (const float2*)(edges + (size_t)gbase * 16);
        #pragma unroll
        for (int k = 0; k < 2; k++) {
            int item = tid + k * 256;          // 0..511 over [row][q]
            int row = item >> 2, qq = item & 3;
            float2 v0 = er[row * 8 + qq];
            float2 v1 = er[row * 8 + qq + 4];
            __half h0, l0, h1, l1, h2v, l2, h3, l3;
            split16(v0.x, h0, l0);  split16(v0.y, h1, l1);
            split16(v1.x, h2v, l2); split16(v1.y, h3, l3);
            EHL[item] = make_uint4(pack_h2(h0, h1), pack_h2(h2v, h3),
                                   pack_h2(l0, l1), pack_h2(l2, l3));
        }
    }
    // ---- Stage states: SP[a][row][q2] = {s[row][8a+2q2], s[row][8a+2q2+1]} ----
    {
        const float4* sv = (const float4*)(states + (size_t)gbase * 32);
        #pragma unroll
        for (int k = 0; k < 4; k++) {
            int idx = tid + k * 256;           // 0..1023 over [row][f4]
            int row = idx >> 3, f4 = idx & 7;
            float4 v = sv[idx];
            int a = f4 >> 1, q2 = (f4 & 1) * 2;
            *(float4*)((float*)SP + ((a * 128 + row) * 4 + q2) * 2) = v;
        }
    }
    __syncthreads();

    // ---- Main: 8 steps of 16 rows ----
    #pragma unroll
    for (int hp = 0; hp < 8; hp++) {
        const int rb = hp * 16;

        const uint4 aA = EHL[(rb + g) * 4 + q];       // rows g
        const uint4 aB = EHL[(rb + 8 + g) * 4 + q];   // rows g+8

        u64 mm01[2] = {0ull, 0ull};            // per ip: packed acc rows g
        u64 mm23[2] = {0ull, 0ull};            //         packed acc rows g+8

        #pragma unroll
        for (int a = 0; a < 4; a++) {
            const u64 s0 = *(const u64*)&SP[a * 512 + (rb + g) * 4 + q];
            const u64 s1 = *(const u64*)&SP[a * 512 + (rb + 8 + g) * 4 + q];

            #pragma unroll
            for (int ip = 0; ip < 2; ip++) {
                const int ct = ip * 4 + a;
                float d[4];
                // piece 1 (Eh*Wh) seeds bias; pieces 2,3 accumulate
                mma16c(d, aA.x, aB.x, aA.y, aB.y, whl[ct].x, whl[ct].y,
                       b2[ct].x, b2[ct].y);
                mma16 (d, aA.x, aB.x, aA.y, aB.y, whl[ct].z, whl[ct].w);
                mma16 (d, aA.z, aB.z, aA.w, aB.w, whl[ct].x, whl[ct].y);

                float r0 = fmaxf(d[0], 0.f), r1 = fmaxf(d[1], 0.f);
                float r2 = fmaxf(d[2], 0.f), r3 = fmaxf(d[3], 0.f);
                fma2(mm01[ip], pack_f2(r0, r1), s0);
                fma2(mm23[ip], pack_f2(r2, r3), s1);
            }
        }

        // ---- Reduce (lo+hi, then quad butterfly) and store ----
        #pragma unroll
        for (int ip = 0; ip < 2; ip++) {
            const int i = cb * 16 + w * 2 + ip;
            float x, y;
            unpack_f2(mm01[ip], x, y);
            float v0 = x + y;
            unpack_f2(mm23[ip], x, y);
            float v1 = x + y;
            v0 += __shfl_xor_sync(0xffffffffu, v0, 1);
            v0 += __shfl_xor_sync(0xffffffffu, v0, 2);
            v1 += __shfl_xor_sync(0xffffffffu, v1, 1);
            v1 += __shfl_xor_sync(0xffffffffu, v1, 2);
            if (q == 0) {
                out[(size_t)(gbase + rb + g) * 32 + i] = v0;
                out[(size_t)(gbase + rb + 8 + g) * 32 + i] = v1;
            }
        }
    }
}

extern "C" void kernel_launch(void* const* d_in, const int* in_sizes, int n_in,
                              void* d_out, int out_size)
{
    const float* states = (const float*)d_in[0];  // [16, 4096, 32]
    const float* edges  = (const float*)d_in[1];  // [16, 4096, 16]
    const float* W      = (const float*)d_in[2];  // [16, 1024]
    const float* b      = (const float*)d_in[3];  // [1024]
    float* out          = (float*)d_out;          // [16, 4096, 32]

    (void)in_sizes; (void)n_in; (void)out_size;

    prep_w<<<16, 256>>>(W);
    edge_net_mma<<<1024, NTHREADS>>>(states, edges, b, out);
}